// round 12
// baseline (speedup 1.0000x reference)
#include <cuda_runtime.h>
#include <cuda_fp16.h>
#include <cstdint>

// ---------------------------------------------------------------------------
// GraphSAGE forward (round 12): 2-pass fp16 HMMA chain, occupancy push.
// vs r11: CTA 64m x 128n (warp 16x64, acc 32 regs) -> 3 CTAs/SM = 24 warps;
// Wl stored RAW (fp16 subnormal, |wl|<min_normal) -> pass 2 needs no scaling.
//   acc(f32) += Aq*Wh ; acc += Aq*Wl        (exact, no scale bookkeeping)
// ---------------------------------------------------------------------------

typedef unsigned int u32;
constexpr int MN = 100000;
constexpr int NE = 3200000;

__device__ float g_he[MN];
__device__ int   g_i64flag;
__device__ __align__(256) __half g_hA[(size_t)MN * 256];
__device__ __align__(256) __half g_hB[(size_t)MN * 256];
__device__ __align__(256) __half g_Wh[7 * 65536];
__device__ __align__(256) __half g_Wl[7 * 65536];   // w - fp16(w), subnormal
__device__ float g_whe[7 * 256];
__device__ float g_bias[7 * 256];

// -------------------- PTX helpers -------------------------------------------
__device__ __forceinline__ u32 smem_u32(const void* p) {
    u32 a;
    asm("{ .reg .u64 t; cvta.to.shared.u64 t, %1; cvt.u32.u64 %0, t; }" : "=r"(a) : "l"(p));
    return a;
}
#define CP_ASYNC16(sm, g) \
    asm volatile("cp.async.cg.shared.global [%0], [%1], 16;" :: "r"(sm), "l"(g))
#define CP_COMMIT() asm volatile("cp.async.commit_group;" ::: "memory")
#define CP_WAIT(n)  asm volatile("cp.async.wait_group %0;" :: "n"(n) : "memory")
#define LDSM_X4(r0, r1, r2, r3, a) \
    asm volatile("ldmatrix.sync.aligned.m8n8.x4.shared.b16 {%0,%1,%2,%3}, [%4];" \
        : "=r"(r0), "=r"(r1), "=r"(r2), "=r"(r3) : "r"(a))

__device__ __forceinline__ void mma_f16(float* d, const u32* a, const u32* b) {
    asm("mma.sync.aligned.m16n8k16.row.col.f32.f16.f16.f32 "
        "{%0,%1,%2,%3}, {%4,%5,%6,%7}, {%8,%9}, {%0,%1,%2,%3};"
        : "+f"(d[0]), "+f"(d[1]), "+f"(d[2]), "+f"(d[3])
        : "r"(a[0]), "r"(a[1]), "r"(a[2]), "r"(a[3]), "r"(b[0]), "r"(b[1]));
}

// -------------------- small kernels -----------------------------------------
__global__ void k_quant_init(const float* __restrict__ A, const void* __restrict__ dst_raw) {
    int i = blockIdx.x * blockDim.x + threadIdx.x;
    if (i == 0) {
        const long long* p = (const long long*)dst_raw;
        int is64 = 1;
        #pragma unroll
        for (int j = 0; j < 4; ++j) {
            long long v = p[j];
            if (v < 0 || v >= (long long)MN) is64 = 0;
        }
        g_i64flag = is64;
    }
    if (i < MN) g_he[i] = 0.0f;
    if (i < MN * 128) g_hA[i] = __float2half_rn(A[i]);
}

__global__ void k_scatter(const float* __restrict__ ef, const void* __restrict__ dst_raw) {
    int i = blockIdx.x * blockDim.x + threadIdx.x;
    if (i >= NE) return;
    int d = g_i64flag ? (int)((const long long*)dst_raw)[i] : ((const int*)dst_raw)[i];
    atomicAdd(&g_he[d], ef[i]);
}

struct WPtrs { const float* W[7]; const float* B[7]; };

__global__ void k_packw_all(WPtrs wp) {
    const int layer = blockIdx.y;
    const int n = blockIdx.x;
    const int tid = threadIdx.x;          // 128
    const int K = (layer == 0) ? 128 : 256;
    const int has_he = (layer < 6) ? 1 : 0;
    const int ld = K + has_he;
    const float* W = wp.W[layer];
    __half* wh = g_Wh + layer * 65536 + n * K;
    __half* wl = g_Wl + layer * 65536 + n * K;
    for (int k = tid; k < K; k += 128) {
        float w = W[(size_t)n * ld + k];
        __half h = __float2half_rn(w);
        wh[k] = h;
        wl[k] = __float2half_rn(w - __half2float(h));   // subnormal fp16, exact-ish
    }
    if (tid == 0) {
        g_whe[layer * 256 + n]  = has_he ? W[(size_t)n * ld + K] : 0.0f;
        g_bias[layer * 256 + n] = wp.B[layer][n];
    }
}

// -------------------- 2-pass fp16 HMMA GEMM ----------------------------------
// C[M,256] = relu(A @ W^T + bias + he ⊗ whe). CTA 64m x 128n, 8 warps
// (wm=wid&3 m16-tile, wn=wid>>2 n64-tile), BK=32, 3-stage cp.async, 3 CTAs/SM.
// Stage 20KB: A 4K | Wh 8K | Wl 8K.
// A plane addr(r,c16)=((c^(r&3))*64+r)*16 ; W planes ((c^(r&3))*128+r)*16.
template<int K, bool HAS_HE>
__global__ __launch_bounds__(256, 3)
void k_mma(const __half* __restrict__ Aq,
           const __half* __restrict__ Wh, const __half* __restrict__ Wl,
           const float* __restrict__ bias, const float* __restrict__ whe,
           const float* __restrict__ he,
           __half* __restrict__ C, int M)
{
    constexpr int NKC = K / 32;
    constexpr u32 STAGE = 20480;
    extern __shared__ __align__(128) char smem[];
    const u32 sb = smem_u32(smem);

    const int tid  = threadIdx.x;
    const int lane = tid & 31;
    const int wid  = tid >> 5;
    const int wm   = wid & 3;        // m16 tile
    const int wn   = wid >> 2;       // n64 tile
    const int bm   = blockIdx.y * 64;
    const int bn   = blockIdx.x * 128;

    // loaders: A 1 transfer/thread, W 4 transfers/thread
    const int ar = tid >> 2, ac = tid & 3;
    const __half* gA = Aq + (size_t)min(bm + ar, M - 1) * K + ac * 8;
    const u32 sA = (u32)((((ac ^ (ar & 3)) << 6) + ar) << 4);

    auto load_stage = [&](int slot, int kc) {
        const u32 base = sb + slot * STAGE;
        const int ko = kc * 32;
        CP_ASYNC16(base + sA, gA + ko);
        #pragma unroll
        for (int i = 0; i < 4; ++i) {
            int idx = tid + i * 256;
            int pln = idx >> 9;              // 0: Wh, 1: Wl
            int rem = idx & 511;
            int r = rem >> 2, c = rem & 3;
            const __half* gw = (pln ? Wl : Wh) + (size_t)(bn + r) * K + ko + c * 8;
            CP_ASYNC16(base + 4096u + (u32)pln * 8192u +
                       (u32)((((c ^ (r & 3)) << 7) + r) << 4), gw);
        }
    };

    float acc[8][4];
    #pragma unroll
    for (int ng = 0; ng < 8; ++ng)
        #pragma unroll
        for (int q = 0; q < 4; ++q) acc[ng][q] = 0.0f;

    load_stage(0, 0); CP_COMMIT();
    load_stage(1, 1); CP_COMMIT();

    const int lr = lane & 15;
    const int lc = lane >> 4;

    #pragma unroll 1
    for (int kc = 0; kc < NKC; ++kc) {
        CP_WAIT(1);
        __syncthreads();
        if (kc + 2 < NKC) load_stage((kc + 2) % 3, kc + 2);
        CP_COMMIT();

        const u32 st = sb + (kc % 3) * STAGE;
        #pragma unroll
        for (int k16 = 0; k16 < 2; ++k16) {
            const int c0i = k16 * 2 + lc;
            u32 Af[4], Bt[8][2];
            {
                const int r = wm * 16 + lr;
                const u32 a0 = st + (u32)(((((c0i ^ (r & 3)) << 6) + r) << 4));
                LDSM_X4(Af[0], Af[1], Af[2], Af[3], a0);
            }
            // ---- pass 1: W-hi ----------------------------------------------
            #pragma unroll
            for (int gp = 0; gp < 4; ++gp) {
                const int r = wn * 64 + gp * 16 + lr;
                const u32 b0 = st + 4096u + (u32)(((((c0i ^ (r & 3)) << 7) + r) << 4));
                u32 t0, t1, t2, t3;
                LDSM_X4(t0, t1, t2, t3, b0);
                Bt[2 * gp][0] = t0; Bt[2 * gp + 1][0] = t1;
                Bt[2 * gp][1] = t2; Bt[2 * gp + 1][1] = t3;
            }
            #pragma unroll
            for (int ng = 0; ng < 8; ++ng)
                mma_f16(acc[ng], Af, Bt[ng]);
            // ---- pass 2: W-lo (raw subnormal, no scaling needed) -------------
            #pragma unroll
            for (int gp = 0; gp < 4; ++gp) {
                const int r = wn * 64 + gp * 16 + lr;
                const u32 b0 = st + 12288u + (u32)(((((c0i ^ (r & 3)) << 7) + r) << 4));
                u32 t0, t1, t2, t3;
                LDSM_X4(t0, t1, t2, t3, b0);
                Bt[2 * gp][0] = t0; Bt[2 * gp + 1][0] = t1;
                Bt[2 * gp][1] = t2; Bt[2 * gp + 1][1] = t3;
            }
            #pragma unroll
            for (int ng = 0; ng < 8; ++ng)
                mma_f16(acc[ng], Af, Bt[ng]);
        }
    }

    // ---- epilogue: bias + he*whe + relu -> fp16, smem-staged stores ---------
    CP_WAIT(0);
    __syncthreads();
    constexpr u32 ROWB = 272;                 // 256B data + 16B pad per row

    float bv[8][2], wv[8][2];
    const int colq = (lane & 3) * 2;
    #pragma unroll
    for (int ng = 0; ng < 8; ++ng) {
        const int cg = bn + wn * 64 + ng * 8 + colq;
        bv[ng][0] = __ldg(&bias[cg]);
        bv[ng][1] = __ldg(&bias[cg + 1]);
        if (HAS_HE) {
            wv[ng][0] = __ldg(&whe[cg]);
            wv[ng][1] = __ldg(&whe[cg + 1]);
        }
    }
    #pragma unroll
    for (int h = 0; h < 2; ++h) {
        const int rl  = wm * 16 + h * 8 + (lane >> 2);
        const int row = bm + rl;
        const float hv = (HAS_HE && row < M) ? __ldg(&he[row]) : 0.0f;
        #pragma unroll
        for (int ng = 0; ng < 8; ++ng) {
            float v0 = acc[ng][2 * h + 0] + bv[ng][0];
            float v1 = acc[ng][2 * h + 1] + bv[ng][1];
            if (HAS_HE) { v0 = fmaf(hv, wv[ng][0], v0); v1 = fmaf(hv, wv[ng][1], v1); }
            __half2 o = __floats2half2_rn(fmaxf(v0, 0.0f), fmaxf(v1, 0.0f));
            *(__half2*)(smem + rl * ROWB + (u32)(wn * 64 + ng * 8 + colq) * 2) = o;
        }
    }
    __syncthreads();

    // coalesced stores: 16 lanes x 16B cover the CTA's 128 fp16 columns
    const int seg = tid & 15;
    const int rr  = tid >> 4;                 // 0..15
    #pragma unroll
    for (int i = 0; i < 4; ++i) {
        const int rl  = rr + i * 16;          // 0..63
        const int row = bm + rl;
        if (row < M)
            *(uint4*)(C + (size_t)row * 256 + bn + seg * 8) =
                *(const uint4*)(smem + rl * ROWB + seg * 16);
    }
}

// -------------------- final GEMV ---------------------------------------------
__global__ void k_gemv(const __half* __restrict__ A,
                       const float* __restrict__ w, const float* __restrict__ b,
                       float* __restrict__ out, int M) {
    __shared__ __align__(16) float wsm[256];
    int tid = threadIdx.x;
    wsm[tid] = w[tid];
    __syncthreads();
    int row  = blockIdx.x * 8 + (tid >> 5);
    int lane = tid & 31;
    if (row >= M) return;
    uint4 v = *(const uint4*)(A + (size_t)row * 256 + lane * 8);
    const __half2* hp = (const __half2*)&v;
    float s = 0.0f;
    #pragma unroll
    for (int q = 0; q < 4; ++q) {
        float2 f = __half22float2(hp[q]);
        s = fmaf(f.x, wsm[lane * 8 + 2 * q], s);
        s = fmaf(f.y, wsm[lane * 8 + 2 * q + 1], s);
    }
    #pragma unroll
    for (int o = 16; o; o >>= 1) s += __shfl_down_sync(0xffffffffu, s, o);
    if (lane == 0) out[row] = s + b[0];
}

// ---------------------------------------------------------------------------
extern "C" void kernel_launch(void* const* d_in, const int* in_sizes, int n_in,
                              void* d_out, int out_size) {
    const float* node_feat = (const float*)d_in[0];
    const float* edge_feat = (const float*)d_in[1];
    const void*  edge_dst  = d_in[2];
    WPtrs wp;
    for (int l = 0; l < 7; ++l) {
        wp.W[l] = (const float*)d_in[3 + 2 * l];
        wp.B[l] = (const float*)d_in[4 + 2 * l];
    }
    const float* Wr3 = (const float*)d_in[17];
    const float* br3 = (const float*)d_in[18];
    float* out = (float*)d_out;

    void* p;
    cudaGetSymbolAddress(&p, g_he);   float* he = (float*)p;
    cudaGetSymbolAddress(&p, g_hA);   __half* hA = (__half*)p;
    cudaGetSymbolAddress(&p, g_hB);   __half* hB = (__half*)p;
    cudaGetSymbolAddress(&p, g_Wh);   __half* Wh = (__half*)p;
    cudaGetSymbolAddress(&p, g_Wl);   __half* Wl = (__half*)p;
    cudaGetSymbolAddress(&p, g_whe);  float* whe  = (float*)p;
    cudaGetSymbolAddress(&p, g_bias); float* bias = (float*)p;

    const int SMEM_DYN = 3 * 20480;   // 60KB
    cudaFuncSetAttribute(k_mma<128, true >, cudaFuncAttributeMaxDynamicSharedMemorySize, SMEM_DYN);
    cudaFuncSetAttribute(k_mma<256, true >, cudaFuncAttributeMaxDynamicSharedMemorySize, SMEM_DYN);
    cudaFuncSetAttribute(k_mma<256, false>, cudaFuncAttributeMaxDynamicSharedMemorySize, SMEM_DYN);

    dim3 grid(2, (MN + 63) / 64);     // (2, 1563)

    // #1: convert A + zero he + dtype detect
    k_quant_init<<<(MN * 128 + 255) / 256, 256>>>(node_feat, edge_dst);
    // #2: he scatter
    k_scatter<<<(NE + 255) / 256, 256>>>(edge_feat, edge_dst);
    // #3: pack all weights
    { dim3 g(256, 7); k_packw_all<<<g, 128>>>(wp); }
    // #4: layer 0  <-- ncu sample slot
    k_mma<128, true ><<<grid, 256, SMEM_DYN>>>(hA, Wh,             Wl,             bias,        whe,        he, hB, MN);
    k_mma<256, true ><<<grid, 256, SMEM_DYN>>>(hB, Wh + 1 * 65536, Wl + 1 * 65536, bias + 256,  whe + 256,  he, hA, MN);
    k_mma<256, true ><<<grid, 256, SMEM_DYN>>>(hA, Wh + 2 * 65536, Wl + 2 * 65536, bias + 512,  whe + 512,  he, hB, MN);
    k_mma<256, true ><<<grid, 256, SMEM_DYN>>>(hB, Wh + 3 * 65536, Wl + 3 * 65536, bias + 768,  whe + 768,  he, hA, MN);
    k_mma<256, true ><<<grid, 256, SMEM_DYN>>>(hA, Wh + 4 * 65536, Wl + 4 * 65536, bias + 1024, whe + 1024, he, hB, MN);
    k_mma<256, true ><<<grid, 256, SMEM_DYN>>>(hB, Wh + 5 * 65536, Wl + 5 * 65536, bias + 1280, whe + 1280, he, hA, MN);
    k_mma<256, false><<<grid, 256, SMEM_DYN>>>(hA, Wh + 6 * 65536, Wl + 6 * 65536, bias + 1536, nullptr,    nullptr, hB, MN);
    // final projection
    k_gemv<<<(MN + 7) / 8, 256>>>(hB, Wr3, br3, out, MN);
}

// round 13
// speedup vs baseline: 1.8569x; 1.8569x over previous
#include <cuda_runtime.h>
#include <cuda_fp16.h>
#include <cstdint>

// ---------------------------------------------------------------------------
// GraphSAGE forward (round 13): single-pass fp16 HMMA chain.
// vs r11: W-lo plane dropped entirely (W = fp16(w)); MMA count halves.
// Error budget: A,W both 2^-11 -> per-layer RMS 3.1e-4 -> final ~4.2e-4
// (calibrated multiplier 1.34 from r11). Tile/pipeline identical to r11.
// ---------------------------------------------------------------------------

typedef unsigned int u32;
constexpr int MN = 100000;
constexpr int NE = 3200000;

__device__ float g_he[MN];
__device__ int   g_i64flag;
__device__ __align__(256) __half g_hA[(size_t)MN * 256];
__device__ __align__(256) __half g_hB[(size_t)MN * 256];
__device__ __align__(256) __half g_Wh[7 * 65536];
__device__ float g_whe[7 * 256];
__device__ float g_bias[7 * 256];

// -------------------- PTX helpers -------------------------------------------
__device__ __forceinline__ u32 smem_u32(const void* p) {
    u32 a;
    asm("{ .reg .u64 t; cvta.to.shared.u64 t, %1; cvt.u32.u64 %0, t; }" : "=r"(a) : "l"(p));
    return a;
}
#define CP_ASYNC16(sm, g) \
    asm volatile("cp.async.cg.shared.global [%0], [%1], 16;" :: "r"(sm), "l"(g))
#define CP_COMMIT() asm volatile("cp.async.commit_group;" ::: "memory")
#define CP_WAIT(n)  asm volatile("cp.async.wait_group %0;" :: "n"(n) : "memory")
#define LDSM_X4(r0, r1, r2, r3, a) \
    asm volatile("ldmatrix.sync.aligned.m8n8.x4.shared.b16 {%0,%1,%2,%3}, [%4];" \
        : "=r"(r0), "=r"(r1), "=r"(r2), "=r"(r3) : "r"(a))

__device__ __forceinline__ void mma_f16(float* d, const u32* a, const u32* b) {
    asm("mma.sync.aligned.m16n8k16.row.col.f32.f16.f16.f32 "
        "{%0,%1,%2,%3}, {%4,%5,%6,%7}, {%8,%9}, {%0,%1,%2,%3};"
        : "+f"(d[0]), "+f"(d[1]), "+f"(d[2]), "+f"(d[3])
        : "r"(a[0]), "r"(a[1]), "r"(a[2]), "r"(a[3]), "r"(b[0]), "r"(b[1]));
}

// -------------------- small kernels -----------------------------------------
__global__ void k_quant_init(const float* __restrict__ A, const void* __restrict__ dst_raw) {
    int i = blockIdx.x * blockDim.x + threadIdx.x;
    if (i == 0) {
        const long long* p = (const long long*)dst_raw;
        int is64 = 1;
        #pragma unroll
        for (int j = 0; j < 4; ++j) {
            long long v = p[j];
            if (v < 0 || v >= (long long)MN) is64 = 0;
        }
        g_i64flag = is64;
    }
    if (i < MN) g_he[i] = 0.0f;
    if (i < MN * 128) g_hA[i] = __float2half_rn(A[i]);
}

__global__ void k_scatter(const float* __restrict__ ef, const void* __restrict__ dst_raw) {
    int i = blockIdx.x * blockDim.x + threadIdx.x;
    if (i >= NE) return;
    int d = g_i64flag ? (int)((const long long*)dst_raw)[i] : ((const int*)dst_raw)[i];
    atomicAdd(&g_he[d], ef[i]);
}

struct WPtrs { const float* W[7]; const float* B[7]; };

__global__ void k_packw_all(WPtrs wp) {
    const int layer = blockIdx.y;
    const int n = blockIdx.x;
    const int tid = threadIdx.x;          // 128
    const int K = (layer == 0) ? 128 : 256;
    const int has_he = (layer < 6) ? 1 : 0;
    const int ld = K + has_he;
    const float* W = wp.W[layer];
    __half* wh = g_Wh + layer * 65536 + n * K;
    for (int k = tid; k < K; k += 128)
        wh[k] = __float2half_rn(W[(size_t)n * ld + k]);
    if (tid == 0) {
        g_whe[layer * 256 + n]  = has_he ? W[(size_t)n * ld + K] : 0.0f;
        g_bias[layer * 256 + n] = wp.B[layer][n];
    }
}

// -------------------- single-pass fp16 HMMA GEMM ------------------------------
// C[M,256] = relu(A @ W^T + bias + he ⊗ whe). CTA 128m x 128n, 8 warps
// (4m x 2n, warp 32x64), BK=32, 3-stage cp.async, 2 CTAs/SM.
// Stage 16KB: A 8K | W 8K. Plane addr(r,c16)=((c^(r&3))*128+r)*16.
template<int K, bool HAS_HE>
__global__ __launch_bounds__(256, 2)
void k_mma(const __half* __restrict__ Aq, const __half* __restrict__ Wh,
           const float* __restrict__ bias, const float* __restrict__ whe,
           const float* __restrict__ he,
           __half* __restrict__ C, int M)
{
    constexpr int NKC = K / 32;
    constexpr u32 STAGE = 16384;
    extern __shared__ __align__(128) char smem[];
    const u32 sb = smem_u32(smem);

    const int tid  = threadIdx.x;
    const int lane = tid & 31;
    const int wid  = tid >> 5;
    const int wm   = wid & 3;
    const int wn   = wid >> 2;
    const int bm   = blockIdx.y * 128;
    const int bn   = blockIdx.x * 128;

    // loader: 4 transfers/thread (A rows r0,r1 ; W rows r0,r1)
    const int r0 = tid >> 2,         c0 = tid & 3;
    const int r1 = r0 + 64;
    const __half* gA0 = Aq + (size_t)min(bm + r0, M - 1) * K + c0 * 8;
    const __half* gA1 = Aq + (size_t)min(bm + r1, M - 1) * K + c0 * 8;
    const __half* gW0 = Wh + (size_t)(bn + r0) * K + c0 * 8;
    const __half* gW1 = Wh + (size_t)(bn + r1) * K + c0 * 8;
    const u32 s0 = (u32)((((c0 ^ (r0 & 3)) << 7) + r0) << 4);
    const u32 s1 = (u32)((((c0 ^ (r1 & 3)) << 7) + r1) << 4);

    auto load_stage = [&](int slot, int kc) {
        const u32 base = sb + slot * STAGE;
        const int ko = kc * 32;
        CP_ASYNC16(base + s0,         gA0 + ko);
        CP_ASYNC16(base + s1,         gA1 + ko);
        CP_ASYNC16(base + 8192u + s0, gW0 + ko);
        CP_ASYNC16(base + 8192u + s1, gW1 + ko);
    };

    float acc[2][8][4];
    #pragma unroll
    for (int mt = 0; mt < 2; ++mt)
        #pragma unroll
        for (int ng = 0; ng < 8; ++ng)
            #pragma unroll
            for (int q = 0; q < 4; ++q) acc[mt][ng][q] = 0.0f;

    load_stage(0, 0); CP_COMMIT();
    load_stage(1, 1); CP_COMMIT();

    const int lr = lane & 15;
    const int lc = lane >> 4;

    #pragma unroll 1
    for (int kc = 0; kc < NKC; ++kc) {
        CP_WAIT(1);
        __syncthreads();
        if (kc + 2 < NKC) load_stage((kc + 2) % 3, kc + 2);
        CP_COMMIT();

        const u32 st = sb + (kc % 3) * STAGE;
        #pragma unroll
        for (int k16 = 0; k16 < 2; ++k16) {
            const int c0i = k16 * 2 + lc;
            u32 Af[2][4], Bt[8][2];
            #pragma unroll
            for (int mt = 0; mt < 2; ++mt) {
                const int r = wm * 32 + mt * 16 + lr;
                const u32 a0 = st + (u32)(((((c0i ^ (r & 3)) << 7) + r) << 4));
                LDSM_X4(Af[mt][0], Af[mt][1], Af[mt][2], Af[mt][3], a0);
            }
            #pragma unroll
            for (int gp = 0; gp < 4; ++gp) {
                const int r = wn * 64 + gp * 16 + lr;
                const u32 b0 = st + 8192u + (u32)(((((c0i ^ (r & 3)) << 7) + r) << 4));
                u32 t0, t1, t2, t3;
                LDSM_X4(t0, t1, t2, t3, b0);
                Bt[2 * gp][0] = t0; Bt[2 * gp + 1][0] = t1;
                Bt[2 * gp][1] = t2; Bt[2 * gp + 1][1] = t3;
            }
            #pragma unroll
            for (int mt = 0; mt < 2; ++mt)
                #pragma unroll
                for (int ng = 0; ng < 8; ++ng)
                    mma_f16(acc[mt][ng], Af[mt], Bt[ng]);
        }
    }

    // ---- epilogue: bias + he*whe + relu -> fp16, smem-staged stores ---------
    CP_WAIT(0);
    __syncthreads();
    constexpr u32 ROWB = 272;                 // 256B data + 16B pad per row

    float bv[8][2], wv[8][2];
    const int colq = (lane & 3) * 2;
    #pragma unroll
    for (int ng = 0; ng < 8; ++ng) {
        const int cg = bn + wn * 64 + ng * 8 + colq;
        bv[ng][0] = __ldg(&bias[cg]);
        bv[ng][1] = __ldg(&bias[cg + 1]);
        if (HAS_HE) {
            wv[ng][0] = __ldg(&whe[cg]);
            wv[ng][1] = __ldg(&whe[cg + 1]);
        }
    }
    #pragma unroll
    for (int mt = 0; mt < 2; ++mt) {
        #pragma unroll
        for (int h = 0; h < 2; ++h) {
            const int rl  = wm * 32 + mt * 16 + h * 8 + (lane >> 2);
            const int row = bm + rl;
            const float hv = (HAS_HE && row < M) ? __ldg(&he[row]) : 0.0f;
            #pragma unroll
            for (int ng = 0; ng < 8; ++ng) {
                float v0 = acc[mt][ng][2 * h + 0] + bv[ng][0];
                float v1 = acc[mt][ng][2 * h + 1] + bv[ng][1];
                if (HAS_HE) { v0 = fmaf(hv, wv[ng][0], v0); v1 = fmaf(hv, wv[ng][1], v1); }
                __half2 o = __floats2half2_rn(fmaxf(v0, 0.0f), fmaxf(v1, 0.0f));
                *(__half2*)(smem + rl * ROWB + (u32)(wn * 64 + ng * 8 + colq) * 2) = o;
            }
        }
    }
    __syncthreads();

    // coalesced stores: 16 lanes x 16B cover the CTA's 128 fp16 columns
    const int seg = tid & 15;
    const int rr  = tid >> 4;                 // 0..15
    #pragma unroll
    for (int i = 0; i < 8; ++i) {
        const int rl  = rr + i * 16;
        const int row = bm + rl;
        if (row < M)
            *(uint4*)(C + (size_t)row * 256 + bn + seg * 8) =
                *(const uint4*)(smem + rl * ROWB + seg * 16);
    }
}

// -------------------- final GEMV ---------------------------------------------
__global__ void k_gemv(const __half* __restrict__ A,
                       const float* __restrict__ w, const float* __restrict__ b,
                       float* __restrict__ out, int M) {
    __shared__ __align__(16) float wsm[256];
    int tid = threadIdx.x;
    wsm[tid] = w[tid];
    __syncthreads();
    int row  = blockIdx.x * 8 + (tid >> 5);
    int lane = tid & 31;
    if (row >= M) return;
    uint4 v = *(const uint4*)(A + (size_t)row * 256 + lane * 8);
    const __half2* hp = (const __half2*)&v;
    float s = 0.0f;
    #pragma unroll
    for (int q = 0; q < 4; ++q) {
        float2 f = __half22float2(hp[q]);
        s = fmaf(f.x, wsm[lane * 8 + 2 * q], s);
        s = fmaf(f.y, wsm[lane * 8 + 2 * q + 1], s);
    }
    #pragma unroll
    for (int o = 16; o; o >>= 1) s += __shfl_down_sync(0xffffffffu, s, o);
    if (lane == 0) out[row] = s + b[0];
}

// ---------------------------------------------------------------------------
extern "C" void kernel_launch(void* const* d_in, const int* in_sizes, int n_in,
                              void* d_out, int out_size) {
    const float* node_feat = (const float*)d_in[0];
    const float* edge_feat = (const float*)d_in[1];
    const void*  edge_dst  = d_in[2];
    WPtrs wp;
    for (int l = 0; l < 7; ++l) {
        wp.W[l] = (const float*)d_in[3 + 2 * l];
        wp.B[l] = (const float*)d_in[4 + 2 * l];
    }
    const float* Wr3 = (const float*)d_in[17];
    const float* br3 = (const float*)d_in[18];
    float* out = (float*)d_out;

    void* p;
    cudaGetSymbolAddress(&p, g_he);   float* he = (float*)p;
    cudaGetSymbolAddress(&p, g_hA);   __half* hA = (__half*)p;
    cudaGetSymbolAddress(&p, g_hB);   __half* hB = (__half*)p;
    cudaGetSymbolAddress(&p, g_Wh);   __half* Wh = (__half*)p;
    cudaGetSymbolAddress(&p, g_whe);  float* whe  = (float*)p;
    cudaGetSymbolAddress(&p, g_bias); float* bias = (float*)p;

    const int SMEM_DYN = 3 * 16384;   // 48KB
    cudaFuncSetAttribute(k_mma<128, true >, cudaFuncAttributeMaxDynamicSharedMemorySize, SMEM_DYN);
    cudaFuncSetAttribute(k_mma<256, true >, cudaFuncAttributeMaxDynamicSharedMemorySize, SMEM_DYN);
    cudaFuncSetAttribute(k_mma<256, false>, cudaFuncAttributeMaxDynamicSharedMemorySize, SMEM_DYN);

    dim3 grid(2, (MN + 127) / 128);   // (2, 782)

    // #1: convert A + zero he + dtype detect
    k_quant_init<<<(MN * 128 + 255) / 256, 256>>>(node_feat, edge_dst);
    // #2: he scatter
    k_scatter<<<(NE + 255) / 256, 256>>>(edge_feat, edge_dst);
    // #3: pack all weights
    { dim3 g(256, 7); k_packw_all<<<g, 128>>>(wp); }
    // #4: layer 0  <-- ncu sample slot
    k_mma<128, true ><<<grid, 256, SMEM_DYN>>>(hA, Wh,             bias,        whe,        he, hB, MN);
    k_mma<256, true ><<<grid, 256, SMEM_DYN>>>(hB, Wh + 1 * 65536, bias + 256,  whe + 256,  he, hA, MN);
    k_mma<256, true ><<<grid, 256, SMEM_DYN>>>(hA, Wh + 2 * 65536, bias + 512,  whe + 512,  he, hB, MN);
    k_mma<256, true ><<<grid, 256, SMEM_DYN>>>(hB, Wh + 3 * 65536, bias + 768,  whe + 768,  he, hA, MN);
    k_mma<256, true ><<<grid, 256, SMEM_DYN>>>(hA, Wh + 4 * 65536, bias + 1024, whe + 1024, he, hB, MN);
    k_mma<256, true ><<<grid, 256, SMEM_DYN>>>(hB, Wh + 5 * 65536, bias + 1280, whe + 1280, he, hA, MN);
    k_mma<256, false><<<grid, 256, SMEM_DYN>>>(hA, Wh + 6 * 65536, bias + 1536, nullptr,    nullptr, hB, MN);
    // final projection
    k_gemv<<<(MN + 7) / 8, 256>>>(hB, Wr3, br3, out, MN);
}